// round 12
// baseline (speedup 1.0000x reference)
#include <cuda_runtime.h>
#include <cuda_bf16.h>
#include <math.h>

#define BS 8
#define D 256
#define L 1024
#define H 8
#define DK 32
#define EPSV 1e-8f

typedef unsigned int u32;
typedef unsigned long long u64;

// ---- f32x2 packed-math helpers ----------------------------------------------
__device__ __forceinline__ u64 f2dup(float x) {
    u64 r; asm("mov.b64 %0, {%1, %1};" : "=l"(r) : "f"(x)); return r;
}
__device__ __forceinline__ u64 f2pack(float lo, float hi) {
    u64 r; asm("mov.b64 %0, {%1, %2};" : "=l"(r) : "f"(lo), "f"(hi)); return r;
}
__device__ __forceinline__ void fma2(u64& d, u64 a, u64 b) {
    asm("fma.rn.f32x2 %0, %1, %2, %0;" : "+l"(d) : "l"(a), "l"(b));
}
__device__ __forceinline__ float2 f2unpack(u64 v) {
    float2 f; asm("mov.b64 {%0, %1}, %2;" : "=f"(f.x), "=f"(f.y) : "l"(v)); return f;
}

// ---- tensor-core helpers ----------------------------------------------------
__device__ __forceinline__ u32 smaddr(const void* p) {
    return (u32)__cvta_generic_to_shared(p);
}
__device__ __forceinline__ void ldsm4(u32& r0, u32& r1, u32& r2, u32& r3, u32 a) {
    asm volatile("ldmatrix.sync.aligned.m8n8.x4.shared.b16 {%0,%1,%2,%3}, [%4];"
        : "=r"(r0), "=r"(r1), "=r"(r2), "=r"(r3) : "r"(a));
}
__device__ __forceinline__ void ldsm4t(u32& r0, u32& r1, u32& r2, u32& r3, u32 a) {
    asm volatile("ldmatrix.sync.aligned.m8n8.x4.trans.shared.b16 {%0,%1,%2,%3}, [%4];"
        : "=r"(r0), "=r"(r1), "=r"(r2), "=r"(r3) : "r"(a));
}
__device__ __forceinline__ void mma16816(float* c, const u32* a, u32 b0, u32 b1) {
    asm volatile("mma.sync.aligned.m16n8k16.row.col.f32.bf16.bf16.f32 "
        "{%0,%1,%2,%3}, {%4,%5,%6,%7}, {%8,%9}, {%0,%1,%2,%3};"
        : "+f"(c[0]), "+f"(c[1]), "+f"(c[2]), "+f"(c[3])
        : "r"(a[0]), "r"(a[1]), "r"(a[2]), "r"(a[3]), "r"(b0), "r"(b1));
}
__device__ __forceinline__ u32 cvtbf2(float hi, float lo) {
    u32 d; asm("cvt.rn.bf16x2.f32 %0, %1, %2;" : "=r"(d) : "f"(hi), "f"(lo)); return d;
}
// split x into (hi bf16 in low16, lo bf16 in high16)
__device__ __forceinline__ u32 packsplit(float x) {
    __nv_bfloat16 hb = __float2bfloat16(x);
    u32 hbits = (u32)__bfloat16_as_ushort(hb);
    float hf = __uint_as_float(hbits << 16);
    __nv_bfloat16 lb = __float2bfloat16(x - hf);
    return ((u32)__bfloat16_as_ushort(lb) << 16) | hbits;
}

// Scratch (device globals)
__device__ u32 g_qp[BS * D * L];    // [bh][c][l] packed (bf16 hi | lo<<16), pre-masked
__device__ u32 g_kp[BS * D * L];
__device__ u32 g_vp[BS * D * L];
__device__ float g_val[BS * L * D]; // [b][l][c]

// ---------------------------------------------------------------------------
// Kernel 1: grouped 1x1 conv projection -> packed bf16 hi/lo planes.
// 1 l per thread, 768 CTAs -> deeper occupancy (latency-bound before).
// ---------------------------------------------------------------------------
__global__ __launch_bounds__(256) void proj_kernel(
    const float* __restrict__ q, const float* __restrict__ k,
    const float* __restrict__ v, const float* __restrict__ mask,
    const float* __restrict__ Wq, const float* __restrict__ Wk,
    const float* __restrict__ Wv)
{
    __shared__ float wt[DK * DK];   // wt[j][i] = W[i][j]
    const int h = blockIdx.y;
    const int z = blockIdx.z;
    const int b = z / 3;
    const int which = z - b * 3;
    const int t = threadIdx.x;

    const float* __restrict__ X = (which == 0) ? q : (which == 1) ? k : v;
    const float* __restrict__ W = (which == 0) ? Wq : (which == 1) ? Wk : Wv;
    u32* __restrict__ O = (which == 0) ? g_qp : (which == 1) ? g_kp : g_vp;

    for (int idx = t; idx < DK * DK; idx += 256) {
        int j = idx >> 5, i = idx & 31;
        wt[j * DK + i] = W[h * DK * DK + i * DK + j];
    }
    __syncthreads();

    const int l = blockIdx.x * 256 + t;
    const float mval = mask[b * L + l];
    const int xbase = (b * D + h * DK) * L + l;
    const int obase = (b * H + h) * DK * L + l;

    float x[DK];
    #pragma unroll
    for (int j = 0; j < DK; j++) x[j] = X[xbase + j * L];

    u64 acc[16];
    #pragma unroll
    for (int i = 0; i < 16; i++) acc[i] = 0ull;

    #pragma unroll
    for (int j = 0; j < DK; j++) {
        u64 xd = f2dup(x[j]);
        #pragma unroll
        for (int q4 = 0; q4 < 8; q4++) {
            float4 w4 = *(const float4*)&wt[j * DK + q4 * 4];
            fma2(acc[q4 * 2 + 0], xd, f2pack(w4.x, w4.y));
            fma2(acc[q4 * 2 + 1], xd, f2pack(w4.z, w4.w));
        }
    }

    #pragma unroll
    for (int ip = 0; ip < 16; ip++) {
        float2 r = f2unpack(acc[ip]);
        O[obase + (2 * ip + 0) * L] = packsplit(r.x * mval);
        O[obase + (2 * ip + 1) * L] = packsplit(r.y * mval);
    }
}

// ---------------------------------------------------------------------------
// Kernel 2: fused attention, bf16x3 tensor-core, chunked softmax.
// NT=128: half the syncs of R11, longer MMA streams. 2 CTAs/SM.
// ---------------------------------------------------------------------------
#define QP 48
#define KP2 136   // u16 pitch for 128-col K/V tiles (272B rows)
#define SM_QSH 0
#define SM_QSL 12288
#define SM_KSH 24576
#define SM_KSL 33280
#define SM_VSH 41984
#define SM_VSL 50688
#define SM_MK  59392
#define SM_TOT 59904

__global__ __launch_bounds__(256, 2) void attn_kernel(const float* __restrict__ mask)
{
    extern __shared__ char smb[];
    unsigned short* Qsh = (unsigned short*)(smb + SM_QSH);  // [m][c]
    unsigned short* Qsl = (unsigned short*)(smb + SM_QSL);
    unsigned short* Ksh = (unsigned short*)(smb + SM_KSH);  // [c][n] 32x128
    unsigned short* Ksl = (unsigned short*)(smb + SM_KSL);
    unsigned short* Vsh = (unsigned short*)(smb + SM_VSH);  // [d][n] 32x128
    unsigned short* Vsl = (unsigned short*)(smb + SM_VSL);
    float* mk = (float*)(smb + SM_MK);

    const int bh = blockIdx.y;
    const int b = bh / H;
    const int row0 = blockIdx.x * 128;

    const u32* __restrict__ qb = g_qp + bh * DK * L;
    const u32* __restrict__ kbp = g_kp + bh * DK * L;
    const u32* __restrict__ vbp = g_vp + bh * DK * L;
    const float* __restrict__ mp = mask + b * L;

    const int t = threadIdx.x;
    const int lane = t & 31;
    const int warp = t >> 5;
    const int R0 = warp * 16;
    const int qid = lane & 3;

    // ---- Q fill: [m][c] hi/lo planes ----
    #pragma unroll
    for (int i = 0; i < 8; i++) {
        int idx = i * 256 + t;
        int m = idx >> 4, cp = idx & 15;
        u32 q0 = qb[(2 * cp + 0) * L + row0 + m];
        u32 q1 = qb[(2 * cp + 1) * L + row0 + m];
        *(u32*)&Qsh[m * QP + 2 * cp] = ((q1 & 0xFFFFu) << 16) | (q0 & 0xFFFFu);
        *(u32*)&Qsl[m * QP + 2 * cp] = (q1 & 0xFFFF0000u) | (q0 >> 16);
    }

    // ---- prefetch K/V tile 0 (128 cols: 8 uint2 each) ----
    uint2 kpre[8], vpre[8];
    #pragma unroll
    for (int i = 0; i < 8; i++) {
        int idx = i * 256 + t;
        int c = idx >> 6, np = idx & 63;
        kpre[i] = *(const uint2*)&kbp[c * L + 2 * np];
        vpre[i] = *(const uint2*)&vbp[c * L + 2 * np];
    }
    float mpre = (t < 128) ? mp[t] : 0.f;

    __syncthreads();

    // ---- Q fragments (persistent) ----
    u32 qah[2][4], qal[2][4];
    #pragma unroll
    for (int kt = 0; kt < 2; kt++) {
        int arow = R0 + (lane & 15);
        int acol = kt * 16 + (lane >> 4) * 8;
        ldsm4(qah[kt][0], qah[kt][1], qah[kt][2], qah[kt][3], smaddr(&Qsh[arow * QP + acol]));
        ldsm4(qal[kt][0], qal[kt][1], qal[kt][2], qal[kt][3], smaddr(&Qsl[arow * QP + acol]));
    }

    float oa[4][4];
    #pragma unroll
    for (int i = 0; i < 4; i++)
        #pragma unroll
        for (int j = 0; j < 4; j++) oa[i][j] = 0.f;
    float ps0 = 0.f, ps1 = 0.f;

    for (int col0 = 0; col0 < L; col0 += 128) {
        __syncthreads();

        #pragma unroll
        for (int i = 0; i < 8; i++) {
            int idx = i * 256 + t;
            int c = idx >> 6, np = idx & 63;
            *(u32*)&Ksh[c * KP2 + 2 * np] = ((kpre[i].y & 0xFFFFu) << 16) | (kpre[i].x & 0xFFFFu);
            *(u32*)&Ksl[c * KP2 + 2 * np] = (kpre[i].y & 0xFFFF0000u) | (kpre[i].x >> 16);
            *(u32*)&Vsh[c * KP2 + 2 * np] = ((vpre[i].y & 0xFFFFu) << 16) | (vpre[i].x & 0xFFFFu);
            *(u32*)&Vsl[c * KP2 + 2 * np] = (vpre[i].y & 0xFFFF0000u) | (vpre[i].x >> 16);
        }
        if (t < 128) mk[t] = mpre;
        __syncthreads();

        int nxt = col0 + 128;
        if (nxt < L) {
            #pragma unroll
            for (int i = 0; i < 8; i++) {
                int idx = i * 256 + t;
                int c = idx >> 6, np = idx & 63;
                kpre[i] = *(const uint2*)&kbp[c * L + nxt + 2 * np];
                vpre[i] = *(const uint2*)&vbp[c * L + nxt + 2 * np];
            }
            mpre = (t < 128) ? mp[nxt + t] : 0.f;
        }

        // ---- per-16-col chunk: QK -> softmax -> PV ----
        #pragma unroll
        for (int ktp = 0; ktp < 8; ktp++) {
            float sa[2][4];
            #pragma unroll
            for (int i = 0; i < 2; i++)
                #pragma unroll
                for (int j = 0; j < 4; j++) sa[i][j] = 0.f;

            #pragma unroll
            for (int kt = 0; kt < 2; kt++) {
                u32 addr_off = (u32)((kt * 16 + (lane & 15)) * KP2 + ktp * 16 + (lane >> 4) * 8);
                u32 bh0, bh1, bh2, bh3, bl0, bl1, bl2, bl3;
                ldsm4t(bh0, bh1, bh2, bh3, smaddr(&Ksh[addr_off]));
                ldsm4t(bl0, bl1, bl2, bl3, smaddr(&Ksl[addr_off]));
                mma16816(sa[0], qah[kt], bh0, bh1);
                mma16816(sa[0], qah[kt], bl0, bl1);
                mma16816(sa[0], qal[kt], bh0, bh1);
                mma16816(sa[1], qah[kt], bh2, bh3);
                mma16816(sa[1], qah[kt], bl2, bl3);
                mma16816(sa[1], qal[kt], bh2, bh3);
            }

            u32 pah[4], pal[4];
            #pragma unroll
            for (int od = 0; od < 2; od++) {
                int nj = 2 * ktp + od;
                float2 mm = *(const float2*)&mk[8 * nj + 2 * qid];
                float p0 = mm.x * __expf(sa[od][0]);
                float p1 = mm.y * __expf(sa[od][1]);
                float p2 = mm.x * __expf(sa[od][2]);
                float p3 = mm.y * __expf(sa[od][3]);
                ps0 += p0 + p1;
                ps1 += p2 + p3;
                u32 h01 = cvtbf2(p1, p0);
                u32 h23 = cvtbf2(p3, p2);
                float hf0 = __uint_as_float(h01 << 16);
                float hf1 = __uint_as_float(h01 & 0xFFFF0000u);
                float hf2 = __uint_as_float(h23 << 16);
                float hf3 = __uint_as_float(h23 & 0xFFFF0000u);
                pah[od * 2 + 0] = h01;
                pah[od * 2 + 1] = h23;
                pal[od * 2 + 0] = cvtbf2(p1 - hf1, p0 - hf0);
                pal[od * 2 + 1] = cvtbf2(p3 - hf3, p2 - hf2);
            }

            #pragma unroll
            for (int db = 0; db < 2; db++) {
                u32 addr_off = (u32)((db * 16 + (lane & 15)) * KP2 + ktp * 16 + (lane >> 4) * 8);
                u32 vh0, vh1, vh2, vh3, vl0, vl1, vl2, vl3;
                ldsm4(vh0, vh1, vh2, vh3, smaddr(&Vsh[addr_off]));
                ldsm4(vl0, vl1, vl2, vl3, smaddr(&Vsl[addr_off]));
                mma16816(oa[2 * db + 0], pah, vh0, vh2);
                mma16816(oa[2 * db + 0], pah, vl0, vl2);
                mma16816(oa[2 * db + 0], pal, vh0, vh2);
                mma16816(oa[2 * db + 1], pah, vh1, vh3);
                mma16816(oa[2 * db + 1], pah, vl1, vl3);
                mma16816(oa[2 * db + 1], pal, vh1, vh3);
            }
        }
    }

    // ---- quad-reduce row sums ----
    ps0 += __shfl_xor_sync(0xFFFFFFFFu, ps0, 1);
    ps0 += __shfl_xor_sync(0xFFFFFFFFu, ps0, 2);
    ps1 += __shfl_xor_sync(0xFFFFFFFFu, ps1, 1);
    ps1 += __shfl_xor_sync(0xFFFFFFFFu, ps1, 2);
    const float inv0 = 1.0f / (ps0 + EPSV);
    const float inv1 = 1.0f / (ps1 + EPSV);

    // ---- store O to g_val[b][row][h*32 + col] ----
    const int h = bh - b * H;
    const int r = row0 + R0 + (lane >> 2);
    const int cbase = h * DK + 2 * qid;
    #pragma unroll
    for (int dj = 0; dj < 4; dj++) {
        *(float2*)&g_val[(size_t)(b * L + r) * D + cbase + 8 * dj] =
            make_float2(oa[dj][0] * inv0, oa[dj][1] * inv0);
        *(float2*)&g_val[(size_t)(b * L + r + 8) * D + cbase + 8 * dj] =
            make_float2(oa[dj][2] * inv1, oa[dj][3] * inv1);
    }
}

// ---------------------------------------------------------------------------
// Kernel 3: out = mask * (Wp @ val + bp)  (known-good fp32 FFMA2 version)
// ---------------------------------------------------------------------------
#define OK_LD 68

__global__ __launch_bounds__(256) void out_kernel(
    const float* __restrict__ Wp, const float* __restrict__ bp,
    const float* __restrict__ mask, float* __restrict__ out)
{
    __shared__ __align__(16) float As[32 * OK_LD];   // [j][l]
    __shared__ __align__(16) float Bsm[32 * OK_LD];  // [j][i]

    const int b = blockIdx.z;
    const int i0 = blockIdx.y * 64;
    const int l0 = blockIdx.x * 64;
    const int t = threadIdx.x;
    const int rg = t >> 4, cg = t & 15;
    const int lr = rg * 4, ic = cg * 4;

    const float* __restrict__ val = g_val + b * L * D;

    int fl[8], fj[8];
    #pragma unroll
    for (int i = 0; i < 8; i++) {
        int idx = i * 256 + t;
        fl[i] = idx >> 5;
        fj[i] = idx & 31;
    }

    float ab[8], bb[8];
    #pragma unroll
    for (int i = 0; i < 8; i++) {
        ab[i] = val[(l0 + fl[i]) * D + fj[i]];
        bb[i] = Wp[(i0 + fl[i]) * D + fj[i]];
    }

    u64 acc2[2][4];
    #pragma unroll
    for (int p = 0; p < 2; p++)
        #pragma unroll
        for (int i = 0; i < 4; i++) acc2[p][i] = 0ull;

    for (int j0 = 0; j0 < D; j0 += 32) {
        __syncthreads();
        #pragma unroll
        for (int i = 0; i < 8; i++) {
            As[fj[i] * OK_LD + fl[i]] = ab[i];
            Bsm[fj[i] * OK_LD + fl[i]] = bb[i];
        }
        __syncthreads();

        int jn = j0 + 32;
        if (jn < D) {
            #pragma unroll
            for (int i = 0; i < 8; i++) {
                ab[i] = val[(l0 + fl[i]) * D + jn + fj[i]];
                bb[i] = Wp[(i0 + fl[i]) * D + jn + fj[i]];
            }
        }

        #pragma unroll
        for (int kk = 0; kk < 32; kk++) {
            float4 av = *(const float4*)&As[kk * OK_LD + lr];
            float4 bv = *(const float4*)&Bsm[kk * OK_LD + ic];
            u64 a01 = f2pack(av.x, av.y);
            u64 a23 = f2pack(av.z, av.w);
            u64 b0 = f2dup(bv.x), b1 = f2dup(bv.y), b2 = f2dup(bv.z), b3 = f2dup(bv.w);
            fma2(acc2[0][0], a01, b0); fma2(acc2[1][0], a23, b0);
            fma2(acc2[0][1], a01, b1); fma2(acc2[1][1], a23, b1);
            fma2(acc2[0][2], a01, b2); fma2(acc2[1][2], a23, b2);
            fma2(acc2[0][3], a01, b3); fma2(acc2[1][3], a23, b3);
        }
    }

    const float bv0 = bp[i0 + ic + 0];
    const float bv1 = bp[i0 + ic + 1];
    const float bv2 = bp[i0 + ic + 2];
    const float bv3 = bp[i0 + ic + 3];

    float2 c0r = f2unpack(acc2[0][0]), c1r = f2unpack(acc2[0][1]);
    float2 c2r = f2unpack(acc2[0][2]), c3r = f2unpack(acc2[0][3]);
    float2 d0r = f2unpack(acc2[1][0]), d1r = f2unpack(acc2[1][1]);
    float2 d2r = f2unpack(acc2[1][2]), d3r = f2unpack(acc2[1][3]);

    float rows[4][4] = {
        {c0r.x, c1r.x, c2r.x, c3r.x},
        {c0r.y, c1r.y, c2r.y, c3r.y},
        {d0r.x, d1r.x, d2r.x, d3r.x},
        {d0r.y, d1r.y, d2r.y, d3r.y},
    };

    #pragma unroll
    for (int p = 0; p < 4; p++) {
        float mv = mask[b * L + l0 + lr + p];
        float4 r;
        r.x = (rows[p][0] + bv0) * mv;
        r.y = (rows[p][1] + bv1) * mv;
        r.z = (rows[p][2] + bv2) * mv;
        r.w = (rows[p][3] + bv3) * mv;
        *(float4*)&out[((size_t)(b * L + l0 + lr + p)) * D + i0 + ic] = r;
    }
}

// ---------------------------------------------------------------------------
extern "C" void kernel_launch(void* const* d_in, const int* in_sizes, int n_in,
                              void* d_out, int out_size)
{
    const float* q    = (const float*)d_in[0];
    const float* k    = (const float*)d_in[1];
    const float* v    = (const float*)d_in[2];
    const float* mask = (const float*)d_in[3];
    const float* Wq   = (const float*)d_in[4];
    const float* Wk   = (const float*)d_in[5];
    const float* Wv   = (const float*)d_in[6];
    const float* Wp   = (const float*)d_in[7];
    const float* bp   = (const float*)d_in[8];
    float* out = (float*)d_out;

    cudaFuncSetAttribute(attn_kernel, cudaFuncAttributeMaxDynamicSharedMemorySize, SM_TOT);

    proj_kernel<<<dim3(L / 256, H, BS * 3), 256>>>(q, k, v, mask, Wq, Wk, Wv);
    attn_kernel<<<dim3(L / 128, BS * H), 256, SM_TOT>>>(mask);
    out_kernel<<<dim3(L / 64, D / 64, BS), 256>>>(Wp, bp, mask, out);
}

// round 13
// speedup vs baseline: 1.0943x; 1.0943x over previous
#include <cuda_runtime.h>
#include <cuda_bf16.h>
#include <math.h>

#define BS 8
#define D 256
#define L 1024
#define H 8
#define DK 32
#define EPSV 1e-8f

typedef unsigned int u32;
typedef unsigned long long u64;

// ---- f32x2 packed-math helpers ----------------------------------------------
__device__ __forceinline__ u64 f2dup(float x) {
    u64 r; asm("mov.b64 %0, {%1, %1};" : "=l"(r) : "f"(x)); return r;
}
__device__ __forceinline__ u64 f2pack(float lo, float hi) {
    u64 r; asm("mov.b64 %0, {%1, %2};" : "=l"(r) : "f"(lo), "f"(hi)); return r;
}
__device__ __forceinline__ void fma2(u64& d, u64 a, u64 b) {
    asm("fma.rn.f32x2 %0, %1, %2, %0;" : "+l"(d) : "l"(a), "l"(b));
}
__device__ __forceinline__ float2 f2unpack(u64 v) {
    float2 f; asm("mov.b64 {%0, %1}, %2;" : "=f"(f.x), "=f"(f.y) : "l"(v)); return f;
}

// ---- tensor-core helpers ----------------------------------------------------
__device__ __forceinline__ u32 smaddr(const void* p) {
    return (u32)__cvta_generic_to_shared(p);
}
__device__ __forceinline__ void ldsm4(u32& r0, u32& r1, u32& r2, u32& r3, u32 a) {
    asm volatile("ldmatrix.sync.aligned.m8n8.x4.shared.b16 {%0,%1,%2,%3}, [%4];"
        : "=r"(r0), "=r"(r1), "=r"(r2), "=r"(r3) : "r"(a));
}
__device__ __forceinline__ void ldsm4t(u32& r0, u32& r1, u32& r2, u32& r3, u32 a) {
    asm volatile("ldmatrix.sync.aligned.m8n8.x4.trans.shared.b16 {%0,%1,%2,%3}, [%4];"
        : "=r"(r0), "=r"(r1), "=r"(r2), "=r"(r3) : "r"(a));
}
__device__ __forceinline__ void mma16816(float* c, const u32* a, u32 b0, u32 b1) {
    asm volatile("mma.sync.aligned.m16n8k16.row.col.f32.bf16.bf16.f32 "
        "{%0,%1,%2,%3}, {%4,%5,%6,%7}, {%8,%9}, {%0,%1,%2,%3};"
        : "+f"(c[0]), "+f"(c[1]), "+f"(c[2]), "+f"(c[3])
        : "r"(a[0]), "r"(a[1]), "r"(a[2]), "r"(a[3]), "r"(b0), "r"(b1));
}
__device__ __forceinline__ u32 cvtbf2(float hi, float lo) {
    u32 d; asm("cvt.rn.bf16x2.f32 %0, %1, %2;" : "=r"(d) : "f"(hi), "f"(lo)); return d;
}
// split x into (hi bf16 in low16, lo bf16 in high16)
__device__ __forceinline__ u32 packsplit(float x) {
    __nv_bfloat16 hb = __float2bfloat16(x);
    u32 hbits = (u32)__bfloat16_as_ushort(hb);
    float hf = __uint_as_float(hbits << 16);
    __nv_bfloat16 lb = __float2bfloat16(x - hf);
    return ((u32)__bfloat16_as_ushort(lb) << 16) | hbits;
}
// cp.async 16B, L2-only path
__device__ __forceinline__ void cpa16(u32 sdst, const void* gsrc) {
    asm volatile("cp.async.cg.shared.global [%0], [%1], 16;" :: "r"(sdst), "l"(gsrc));
}

// Scratch (device globals)
__device__ u32 g_qp[BS * D * L];        // [bh][c][l] packed (hi | lo<<16), pre-masked
__device__ u32 g_kh[BS * D * L / 2];    // [bh][c][l] hi plane (u16, stored as u32 pairs)
__device__ u32 g_kl[BS * D * L / 2];    // lo plane
__device__ u32 g_vh[BS * D * L / 2];
__device__ u32 g_vl[BS * D * L / 2];
__device__ float g_val[BS * L * D];     // [b][l][c]

// ---------------------------------------------------------------------------
// Kernel 1: grouped 1x1 conv projection. 2 adjacent l's per thread.
// Q -> packed plane (for in-kernel transpose); K/V -> separate hi/lo planes
// (cp.async-ready layout for attn).
// ---------------------------------------------------------------------------
__global__ __launch_bounds__(256) void proj_kernel(
    const float* __restrict__ q, const float* __restrict__ k,
    const float* __restrict__ v, const float* __restrict__ mask,
    const float* __restrict__ Wq, const float* __restrict__ Wk,
    const float* __restrict__ Wv)
{
    __shared__ float wt[DK * DK];   // wt[j][i] = W[i][j]
    const int h = blockIdx.y;
    const int z = blockIdx.z;
    const int b = z / 3;
    const int which = z - b * 3;
    const int t = threadIdx.x;

    const float* __restrict__ X = (which == 0) ? q : (which == 1) ? k : v;
    const float* __restrict__ W = (which == 0) ? Wq : (which == 1) ? Wk : Wv;

    for (int idx = t; idx < DK * DK; idx += 256) {
        int j = idx >> 5, i = idx & 31;
        wt[j * DK + i] = W[h * DK * DK + i * DK + j];
    }
    __syncthreads();

    const int l0 = blockIdx.x * 512 + t * 2;
    const float mv0 = mask[b * L + l0];
    const float mv1 = mask[b * L + l0 + 1];
    const int xbase = (b * D + h * DK) * L + l0;

    u64 acc[2][16];
    #pragma unroll
    for (int p = 0; p < 2; p++)
        #pragma unroll
        for (int i = 0; i < 16; i++) acc[p][i] = 0ull;

    #pragma unroll
    for (int j = 0; j < DK; j++) {
        float2 xv = *(const float2*)&X[xbase + j * L];
        u64 x0 = f2dup(xv.x);
        u64 x1 = f2dup(xv.y);
        #pragma unroll
        for (int q4 = 0; q4 < 8; q4++) {
            float4 w4 = *(const float4*)&wt[j * DK + q4 * 4];
            u64 wp0 = f2pack(w4.x, w4.y);
            u64 wp1 = f2pack(w4.z, w4.w);
            fma2(acc[0][q4 * 2 + 0], x0, wp0);
            fma2(acc[0][q4 * 2 + 1], x0, wp1);
            fma2(acc[1][q4 * 2 + 0], x1, wp0);
            fma2(acc[1][q4 * 2 + 1], x1, wp1);
        }
    }

    if (which == 0) {
        const int obase = (b * H + h) * DK * L + l0;
        #pragma unroll
        for (int ip = 0; ip < 16; ip++) {
            float2 r0 = f2unpack(acc[0][ip]);
            float2 r1 = f2unpack(acc[1][ip]);
            uint2 s0, s1;
            s0.x = packsplit(r0.x * mv0); s0.y = packsplit(r1.x * mv1);
            s1.x = packsplit(r0.y * mv0); s1.y = packsplit(r1.y * mv1);
            *(uint2*)&g_qp[obase + (2 * ip + 0) * L] = s0;
            *(uint2*)&g_qp[obase + (2 * ip + 1) * L] = s1;
        }
    } else {
        u32* __restrict__ Oh = (which == 1) ? g_kh : g_vh;
        u32* __restrict__ Ol = (which == 1) ? g_kl : g_vl;
        const int obase2 = (((b * H + h) * DK) * L + l0) >> 1;   // u32 index
        #pragma unroll
        for (int ip = 0; ip < 16; ip++) {
            float2 r0 = f2unpack(acc[0][ip]);
            float2 r1 = f2unpack(acc[1][ip]);
            // channel 2ip
            u32 sa0 = packsplit(r0.x * mv0);     // l0
            u32 sa1 = packsplit(r1.x * mv1);     // l0+1
            Oh[obase2 + (2 * ip + 0) * (L / 2)] = ((sa1 & 0xFFFFu) << 16) | (sa0 & 0xFFFFu);
            Ol[obase2 + (2 * ip + 0) * (L / 2)] = (sa1 & 0xFFFF0000u) | (sa0 >> 16);
            // channel 2ip+1
            u32 sb0 = packsplit(r0.y * mv0);
            u32 sb1 = packsplit(r1.y * mv1);
            Oh[obase2 + (2 * ip + 1) * (L / 2)] = ((sb1 & 0xFFFFu) << 16) | (sb0 & 0xFFFFu);
            Ol[obase2 + (2 * ip + 1) * (L / 2)] = (sb1 & 0xFFFF0000u) | (sb0 >> 16);
        }
    }
}

// ---------------------------------------------------------------------------
// Kernel 2: fused attention, bf16x3 tensor-core, chunked softmax (R11 compute),
// cp.async double-buffered K/V tiles (no register prefetch).
// ---------------------------------------------------------------------------
#define QP 48
#define KP 72
#define SM_QSH 0
#define SM_QSL 12288
#define SM_STG 24576            // stage bases: + stage*18432
#define STG_BYTES 18432         // 4 planes x 32*72*2B
#define PL_BYTES 4608
#define SM_MK  61440            // 2 x 64 floats
#define SM_TOT 61952

__global__ __launch_bounds__(256, 2) void attn_kernel(const float* __restrict__ mask)
{
    extern __shared__ char smb[];
    unsigned short* Qsh = (unsigned short*)(smb + SM_QSH);  // [m][c]
    unsigned short* Qsl = (unsigned short*)(smb + SM_QSL);

    const int bh = blockIdx.y;
    const int b = bh / H;
    const int row0 = blockIdx.x * 128;

    const u32* __restrict__ qb = g_qp + bh * DK * L;
    const unsigned short* __restrict__ khg = (const unsigned short*)g_kh + (size_t)bh * DK * L;
    const unsigned short* __restrict__ klg = (const unsigned short*)g_kl + (size_t)bh * DK * L;
    const unsigned short* __restrict__ vhg = (const unsigned short*)g_vh + (size_t)bh * DK * L;
    const unsigned short* __restrict__ vlg = (const unsigned short*)g_vl + (size_t)bh * DK * L;
    const float* __restrict__ mp = mask + b * L;

    const int t = threadIdx.x;
    const int lane = t & 31;
    const int warp = t >> 5;
    const int R0 = warp * 16;
    const int qid = lane & 3;

    // cp.async fill coords: 32 rows x 8 chunks of 16B per plane
    const int fc = t >> 3;          // channel row 0..31
    const int fch = t & 7;          // 16B chunk 0..7
    const size_t gofs = (size_t)fc * L + fch * 8;    // u16 elements (+ col0 later)
    const u32 sofs = (u32)(fc * (KP * 2) + fch * 16);  // bytes within plane

    // ---- Q fill: [m][c] hi/lo planes ----
    #pragma unroll
    for (int i = 0; i < 8; i++) {
        int idx = i * 256 + t;
        int m = idx >> 4, cp = idx & 15;
        u32 q0 = qb[(2 * cp + 0) * L + row0 + m];
        u32 q1 = qb[(2 * cp + 1) * L + row0 + m];
        *(u32*)&Qsh[m * QP + 2 * cp] = ((q1 & 0xFFFFu) << 16) | (q0 & 0xFFFFu);
        *(u32*)&Qsl[m * QP + 2 * cp] = (q1 & 0xFFFF0000u) | (q0 >> 16);
    }

    // ---- issue tile 0 loads ----
    {
        u32 sb0 = smaddr(smb + SM_STG) + sofs;
        cpa16(sb0,                 khg + gofs);
        cpa16(sb0 + PL_BYTES,      klg + gofs);
        cpa16(sb0 + 2 * PL_BYTES,  vhg + gofs);
        cpa16(sb0 + 3 * PL_BYTES,  vlg + gofs);
        if (t < 16) cpa16(smaddr(smb + SM_MK) + t * 16, mp + t * 4);
    }
    asm volatile("cp.async.commit_group;");

    __syncthreads();   // Q planes visible

    // ---- Q fragments (persistent) ----
    u32 qah[2][4], qal[2][4];
    #pragma unroll
    for (int kt = 0; kt < 2; kt++) {
        int arow = R0 + (lane & 15);
        int acol = kt * 16 + (lane >> 4) * 8;
        ldsm4(qah[kt][0], qah[kt][1], qah[kt][2], qah[kt][3], smaddr(&Qsh[arow * QP + acol]));
        ldsm4(qal[kt][0], qal[kt][1], qal[kt][2], qal[kt][3], smaddr(&Qsl[arow * QP + acol]));
    }

    float oa[4][4];
    #pragma unroll
    for (int i = 0; i < 4; i++)
        #pragma unroll
        for (int j = 0; j < 4; j++) oa[i][j] = 0.f;
    float ps0 = 0.f, ps1 = 0.f;

    const int NTILES = L / 64;
    for (int it = 0; it < NTILES; it++) {
        const int cur = it & 1;

        // issue next tile into the other stage
        if (it + 1 < NTILES) {
            int col0n = (it + 1) * 64;
            u32 sbn = smaddr(smb + SM_STG + (cur ^ 1) * STG_BYTES) + sofs;
            cpa16(sbn,                khg + gofs + col0n);
            cpa16(sbn + PL_BYTES,     klg + gofs + col0n);
            cpa16(sbn + 2 * PL_BYTES, vhg + gofs + col0n);
            cpa16(sbn + 3 * PL_BYTES, vlg + gofs + col0n);
            if (t < 16) cpa16(smaddr(smb + SM_MK + (cur ^ 1) * 256) + t * 16, mp + col0n + t * 4);
        }
        asm volatile("cp.async.commit_group;");
        asm volatile("cp.async.wait_group 1;");
        __syncthreads();   // tile `it` visible to all threads

        unsigned short* Ksh = (unsigned short*)(smb + SM_STG + cur * STG_BYTES);
        unsigned short* Ksl = (unsigned short*)(smb + SM_STG + cur * STG_BYTES + PL_BYTES);
        unsigned short* Vsh = (unsigned short*)(smb + SM_STG + cur * STG_BYTES + 2 * PL_BYTES);
        unsigned short* Vsl = (unsigned short*)(smb + SM_STG + cur * STG_BYTES + 3 * PL_BYTES);
        const float* mk = (const float*)(smb + SM_MK + cur * 256);

        // ---- per-16-col chunk: QK -> softmax -> PV ----
        #pragma unroll
        for (int ktp = 0; ktp < 4; ktp++) {
            float sa[2][4];
            #pragma unroll
            for (int i = 0; i < 2; i++)
                #pragma unroll
                for (int j = 0; j < 4; j++) sa[i][j] = 0.f;

            #pragma unroll
            for (int kt = 0; kt < 2; kt++) {
                u32 addr_off = (u32)((kt * 16 + (lane & 15)) * KP + ktp * 16 + (lane >> 4) * 8);
                u32 bh0, bh1, bh2, bh3, bl0, bl1, bl2, bl3;
                ldsm4t(bh0, bh1, bh2, bh3, smaddr(&Ksh[addr_off]));
                ldsm4t(bl0, bl1, bl2, bl3, smaddr(&Ksl[addr_off]));
                mma16816(sa[0], qah[kt], bh0, bh1);
                mma16816(sa[0], qah[kt], bl0, bl1);
                mma16816(sa[0], qal[kt], bh0, bh1);
                mma16816(sa[1], qah[kt], bh2, bh3);
                mma16816(sa[1], qah[kt], bl2, bl3);
                mma16816(sa[1], qal[kt], bh2, bh3);
            }

            u32 pah[4], pal[4];
            #pragma unroll
            for (int od = 0; od < 2; od++) {
                int nj = 2 * ktp + od;
                float2 mm = *(const float2*)&mk[8 * nj + 2 * qid];
                float p0 = mm.x * __expf(sa[od][0]);
                float p1 = mm.y * __expf(sa[od][1]);
                float p2 = mm.x * __expf(sa[od][2]);
                float p3 = mm.y * __expf(sa[od][3]);
                ps0 += p0 + p1;
                ps1 += p2 + p3;
                u32 h01 = cvtbf2(p1, p0);
                u32 h23 = cvtbf2(p3, p2);
                float hf0 = __uint_as_float(h01 << 16);
                float hf1 = __uint_as_float(h01 & 0xFFFF0000u);
                float hf2 = __uint_as_float(h23 << 16);
                float hf3 = __uint_as_float(h23 & 0xFFFF0000u);
                pah[od * 2 + 0] = h01;
                pah[od * 2 + 1] = h23;
                pal[od * 2 + 0] = cvtbf2(p1 - hf1, p0 - hf0);
                pal[od * 2 + 1] = cvtbf2(p3 - hf3, p2 - hf2);
            }

            #pragma unroll
            for (int db = 0; db < 2; db++) {
                u32 addr_off = (u32)((db * 16 + (lane & 15)) * KP + ktp * 16 + (lane >> 4) * 8);
                u32 vh0, vh1, vh2, vh3, vl0, vl1, vl2, vl3;
                ldsm4(vh0, vh1, vh2, vh3, smaddr(&Vsh[addr_off]));
                ldsm4(vl0, vl1, vl2, vl3, smaddr(&Vsl[addr_off]));
                mma16816(oa[2 * db + 0], pah, vh0, vh2);
                mma16816(oa[2 * db + 0], pah, vl0, vl2);
                mma16816(oa[2 * db + 0], pal, vh0, vh2);
                mma16816(oa[2 * db + 1], pah, vh1, vh3);
                mma16816(oa[2 * db + 1], pah, vl1, vl3);
                mma16816(oa[2 * db + 1], pal, vh1, vh3);
            }
        }
        __syncthreads();   // all reads of stage `cur` done before it is refilled
    }

    // ---- quad-reduce row sums ----
    ps0 += __shfl_xor_sync(0xFFFFFFFFu, ps0, 1);
    ps0 += __shfl_xor_sync(0xFFFFFFFFu, ps0, 2);
    ps1 += __shfl_xor_sync(0xFFFFFFFFu, ps1, 1);
    ps1 += __shfl_xor_sync(0xFFFFFFFFu, ps1, 2);
    const float inv0 = 1.0f / (ps0 + EPSV);
    const float inv1 = 1.0f / (ps1 + EPSV);

    // ---- store O to g_val[b][row][h*32 + col] ----
    const int h = bh - b * H;
    const int r = row0 + R0 + (lane >> 2);
    const int cbase = h * DK + 2 * qid;
    #pragma unroll
    for (int dj = 0; dj < 4; dj++) {
        *(float2*)&g_val[(size_t)(b * L + r) * D + cbase + 8 * dj] =
            make_float2(oa[dj][0] * inv0, oa[dj][1] * inv0);
        *(float2*)&g_val[(size_t)(b * L + r + 8) * D + cbase + 8 * dj] =
            make_float2(oa[dj][2] * inv1, oa[dj][3] * inv1);
    }
}

// ---------------------------------------------------------------------------
// Kernel 3: out = mask * (Wp @ val + bp)  (known-good fp32 FFMA2 version)
// ---------------------------------------------------------------------------
#define OK_LD 68

__global__ __launch_bounds__(256) void out_kernel(
    const float* __restrict__ Wp, const float* __restrict__ bp,
    const float* __restrict__ mask, float* __restrict__ out)
{
    __shared__ __align__(16) float As[32 * OK_LD];   // [j][l]
    __shared__ __align__(16) float Bsm[32 * OK_LD];  // [j][i]

    const int b = blockIdx.z;
    const int i0 = blockIdx.y * 64;
    const int l0 = blockIdx.x * 64;
    const int t = threadIdx.x;
    const int rg = t >> 4, cg = t & 15;
    const int lr = rg * 4, ic = cg * 4;

    const float* __restrict__ val = g_val + b * L * D;

    int fl[8], fj[8];
    #pragma unroll
    for (int i = 0; i < 8; i++) {
        int idx = i * 256 + t;
        fl[i] = idx >> 5;
        fj[i] = idx & 31;
    }

    float ab[8], bb[8];
    #pragma unroll
    for (int i = 0; i < 8; i++) {
        ab[i] = val[(l0 + fl[i]) * D + fj[i]];
        bb[i] = Wp[(i0 + fl[i]) * D + fj[i]];
    }

    u64 acc2[2][4];
    #pragma unroll
    for (int p = 0; p < 2; p++)
        #pragma unroll
        for (int i = 0; i < 4; i++) acc2[p][i] = 0ull;

    for (int j0 = 0; j0 < D; j0 += 32) {
        __syncthreads();
        #pragma unroll
        for (int i = 0; i < 8; i++) {
            As[fj[i] * OK_LD + fl[i]] = ab[i];
            Bsm[fj[i] * OK_LD + fl[i]] = bb[i];
        }
        __syncthreads();

        int jn = j0 + 32;
        if (jn < D) {
            #pragma unroll
            for (int i = 0; i < 8; i++) {
                ab[i] = val[(l0 + fl[i]) * D + jn + fj[i]];
                bb[i] = Wp[(i0 + fl[i]) * D + jn + fj[i]];
            }
        }

        #pragma unroll
        for (int kk = 0; kk < 32; kk++) {
            float4 av = *(const float4*)&As[kk * OK_LD + lr];
            float4 bv = *(const float4*)&Bsm[kk * OK_LD + ic];
            u64 a01 = f2pack(av.x, av.y);
            u64 a23 = f2pack(av.z, av.w);
            u64 b0 = f2dup(bv.x), b1 = f2dup(bv.y), b2 = f2dup(bv.z), b3 = f2dup(bv.w);
            fma2(acc2[0][0], a01, b0); fma2(acc2[1][0], a23, b0);
            fma2(acc2[0][1], a01, b1); fma2(acc2[1][1], a23, b1);
            fma2(acc2[0][2], a01, b2); fma2(acc2[1][2], a23, b2);
            fma2(acc2[0][3], a01, b3); fma2(acc2[1][3], a23, b3);
        }
    }

    const float bv0 = bp[i0 + ic + 0];
    const float bv1 = bp[i0 + ic + 1];
    const float bv2 = bp[i0 + ic + 2];
    const float bv3 = bp[i0 + ic + 3];

    float2 c0r = f2unpack(acc2[0][0]), c1r = f2unpack(acc2[0][1]);
    float2 c2r = f2unpack(acc2[0][2]), c3r = f2unpack(acc2[0][3]);
    float2 d0r = f2unpack(acc2[1][0]), d1r = f2unpack(acc2[1][1]);
    float2 d2r = f2unpack(acc2[1][2]), d3r = f2unpack(acc2[1][3]);

    float rows[4][4] = {
        {c0r.x, c1r.x, c2r.x, c3r.x},
        {c0r.y, c1r.y, c2r.y, c3r.y},
        {d0r.x, d1r.x, d2r.x, d3r.x},
        {d0r.y, d1r.y, d2r.y, d3r.y},
    };

    #pragma unroll
    for (int p = 0; p < 4; p++) {
        float mv = mask[b * L + l0 + lr + p];
        float4 r;
        r.x = (rows[p][0] + bv0) * mv;
        r.y = (rows[p][1] + bv1) * mv;
        r.z = (rows[p][2] + bv2) * mv;
        r.w = (rows[p][3] + bv3) * mv;
        *(float4*)&out[((size_t)(b * L + l0 + lr + p)) * D + i0 + ic] = r;
    }
}

// ---------------------------------------------------------------------------
extern "C" void kernel_launch(void* const* d_in, const int* in_sizes, int n_in,
                              void* d_out, int out_size)
{
    const float* q    = (const float*)d_in[0];
    const float* k    = (const float*)d_in[1];
    const float* v    = (const float*)d_in[2];
    const float* mask = (const float*)d_in[3];
    const float* Wq   = (const float*)d_in[4];
    const float* Wk   = (const float*)d_in[5];
    const float* Wv   = (const float*)d_in[6];
    const float* Wp   = (const float*)d_in[7];
    const float* bp   = (const float*)d_in[8];
    float* out = (float*)d_out;

    cudaFuncSetAttribute(attn_kernel, cudaFuncAttributeMaxDynamicSharedMemorySize, SM_TOT);

    proj_kernel<<<dim3(L / 512, H, BS * 3), 256>>>(q, k, v, mask, Wq, Wk, Wv);
    attn_kernel<<<dim3(L / 128, BS * H), 256, SM_TOT>>>(mask);
    out_kernel<<<dim3(L / 64, D / 64, BS), 256>>>(Wp, bp, mask, out);
}

// round 15
// speedup vs baseline: 1.3163x; 1.2028x over previous
#include <cuda_runtime.h>
#include <cuda_bf16.h>
#include <math.h>

#define BS 8
#define D 256
#define L 1024
#define H 8
#define DK 32
#define EPSV 1e-8f

typedef unsigned int u32;
typedef unsigned long long u64;

// ---- f32x2 packed-math helpers ----------------------------------------------
__device__ __forceinline__ u64 f2dup(float x) {
    u64 r; asm("mov.b64 %0, {%1, %1};" : "=l"(r) : "f"(x)); return r;
}
__device__ __forceinline__ u64 f2pack(float lo, float hi) {
    u64 r; asm("mov.b64 %0, {%1, %2};" : "=l"(r) : "f"(lo), "f"(hi)); return r;
}
__device__ __forceinline__ void fma2(u64& d, u64 a, u64 b) {
    asm("fma.rn.f32x2 %0, %1, %2, %0;" : "+l"(d) : "l"(a), "l"(b));
}
__device__ __forceinline__ float2 f2unpack(u64 v) {
    float2 f; asm("mov.b64 {%0, %1}, %2;" : "=f"(f.x), "=f"(f.y) : "l"(v)); return f;
}

// ---- tensor-core helpers ----------------------------------------------------
__device__ __forceinline__ u32 smaddr(const void* p) {
    return (u32)__cvta_generic_to_shared(p);
}
__device__ __forceinline__ void ldsm4(u32& r0, u32& r1, u32& r2, u32& r3, u32 a) {
    asm volatile("ldmatrix.sync.aligned.m8n8.x4.shared.b16 {%0,%1,%2,%3}, [%4];"
        : "=r"(r0), "=r"(r1), "=r"(r2), "=r"(r3) : "r"(a));
}
__device__ __forceinline__ void ldsm4t(u32& r0, u32& r1, u32& r2, u32& r3, u32 a) {
    asm volatile("ldmatrix.sync.aligned.m8n8.x4.trans.shared.b16 {%0,%1,%2,%3}, [%4];"
        : "=r"(r0), "=r"(r1), "=r"(r2), "=r"(r3) : "r"(a));
}
__device__ __forceinline__ void mma16816(float* c, const u32* a, u32 b0, u32 b1) {
    asm volatile("mma.sync.aligned.m16n8k16.row.col.f32.bf16.bf16.f32 "
        "{%0,%1,%2,%3}, {%4,%5,%6,%7}, {%8,%9}, {%0,%1,%2,%3};"
        : "+f"(c[0]), "+f"(c[1]), "+f"(c[2]), "+f"(c[3])
        : "r"(a[0]), "r"(a[1]), "r"(a[2]), "r"(a[3]), "r"(b0), "r"(b1));
}
__device__ __forceinline__ u32 cvtbf2(float hi, float lo) {
    u32 d; asm("cvt.rn.bf16x2.f32 %0, %1, %2;" : "=r"(d) : "f"(hi), "f"(lo)); return d;
}
// split x into (hi bf16 in low16, lo bf16 in high16)
__device__ __forceinline__ u32 packsplit(float x) {
    __nv_bfloat16 hb = __float2bfloat16(x);
    u32 hbits = (u32)__bfloat16_as_ushort(hb);
    float hf = __uint_as_float(hbits << 16);
    __nv_bfloat16 lb = __float2bfloat16(x - hf);
    return ((u32)__bfloat16_as_ushort(lb) << 16) | hbits;
}
// cp.async 16B, L2-only path
__device__ __forceinline__ void cpa16(u32 sdst, const void* gsrc) {
    asm volatile("cp.async.cg.shared.global [%0], [%1], 16;" :: "r"(sdst), "l"(gsrc));
}

// Scratch (device globals)
__device__ u32 g_qp[BS * D * L];        // [bh][c][l] packed (hi | lo<<16), pre-masked
__device__ u32 g_kh[BS * D * L / 2];    // [bh][c][l] hi plane (u16 pairs)
__device__ u32 g_kl[BS * D * L / 2];
__device__ u32 g_vh[BS * D * L / 2];
__device__ u32 g_vl[BS * D * L / 2];
__device__ unsigned short g_oh[BS * L * D];   // attn output hi plane [b][l][c]
__device__ unsigned short g_ol[BS * L * D];   // attn output lo plane
__device__ unsigned short g_wph[D * D];       // Wp hi plane [j][i]
__device__ unsigned short g_wpl[D * D];       // Wp lo plane

// ---------------------------------------------------------------------------
// Kernel 0: split+transpose Wp into hi/lo u16 planes [j][i].
// ---------------------------------------------------------------------------
__global__ __launch_bounds__(256) void wsplit_kernel(const float* __restrict__ Wp)
{
    int idx = blockIdx.x * 256 + threadIdx.x;
    int j = idx >> 8, i = idx & 255;
    u32 s = packsplit(Wp[i * D + j]);
    g_wph[j * D + i] = (unsigned short)(s & 0xFFFFu);
    g_wpl[j * D + i] = (unsigned short)(s >> 16);
}

// ---------------------------------------------------------------------------
// Kernel 1: grouped 1x1 conv projection. 2 adjacent l's per thread.
// ---------------------------------------------------------------------------
__global__ __launch_bounds__(256) void proj_kernel(
    const float* __restrict__ q, const float* __restrict__ k,
    const float* __restrict__ v, const float* __restrict__ mask,
    const float* __restrict__ Wq, const float* __restrict__ Wk,
    const float* __restrict__ Wv)
{
    __shared__ float wt[DK * DK];   // wt[j][i] = W[i][j]
    const int h = blockIdx.y;
    const int z = blockIdx.z;
    const int b = z / 3;
    const int which = z - b * 3;
    const int t = threadIdx.x;

    const float* __restrict__ X = (which == 0) ? q : (which == 1) ? k : v;
    const float* __restrict__ W = (which == 0) ? Wq : (which == 1) ? Wk : Wv;

    for (int idx = t; idx < DK * DK; idx += 256) {
        int j = idx >> 5, i = idx & 31;
        wt[j * DK + i] = W[h * DK * DK + i * DK + j];
    }
    __syncthreads();

    const int l0 = blockIdx.x * 512 + t * 2;
    const float mv0 = mask[b * L + l0];
    const float mv1 = mask[b * L + l0 + 1];
    const int xbase = (b * D + h * DK) * L + l0;

    u64 acc[2][16];
    #pragma unroll
    for (int p = 0; p < 2; p++)
        #pragma unroll
        for (int i = 0; i < 16; i++) acc[p][i] = 0ull;

    #pragma unroll
    for (int j = 0; j < DK; j++) {
        float2 xv = *(const float2*)&X[xbase + j * L];
        u64 x0 = f2dup(xv.x);
        u64 x1 = f2dup(xv.y);
        #pragma unroll
        for (int q4 = 0; q4 < 8; q4++) {
            float4 w4 = *(const float4*)&wt[j * DK + q4 * 4];
            u64 wp0 = f2pack(w4.x, w4.y);
            u64 wp1 = f2pack(w4.z, w4.w);
            fma2(acc[0][q4 * 2 + 0], x0, wp0);
            fma2(acc[0][q4 * 2 + 1], x0, wp1);
            fma2(acc[1][q4 * 2 + 0], x1, wp0);
            fma2(acc[1][q4 * 2 + 1], x1, wp1);
        }
    }

    if (which == 0) {
        const int obase = (b * H + h) * DK * L + l0;
        #pragma unroll
        for (int ip = 0; ip < 16; ip++) {
            float2 r0 = f2unpack(acc[0][ip]);
            float2 r1 = f2unpack(acc[1][ip]);
            uint2 s0, s1;
            s0.x = packsplit(r0.x * mv0); s0.y = packsplit(r1.x * mv1);
            s1.x = packsplit(r0.y * mv0); s1.y = packsplit(r1.y * mv1);
            *(uint2*)&g_qp[obase + (2 * ip + 0) * L] = s0;
            *(uint2*)&g_qp[obase + (2 * ip + 1) * L] = s1;
        }
    } else {
        u32* __restrict__ Oh = (which == 1) ? g_kh : g_vh;
        u32* __restrict__ Ol = (which == 1) ? g_kl : g_vl;
        const int obase2 = (((b * H + h) * DK) * L + l0) >> 1;
        #pragma unroll
        for (int ip = 0; ip < 16; ip++) {
            float2 r0 = f2unpack(acc[0][ip]);
            float2 r1 = f2unpack(acc[1][ip]);
            u32 sa0 = packsplit(r0.x * mv0);
            u32 sa1 = packsplit(r1.x * mv1);
            Oh[obase2 + (2 * ip + 0) * (L / 2)] = ((sa1 & 0xFFFFu) << 16) | (sa0 & 0xFFFFu);
            Ol[obase2 + (2 * ip + 0) * (L / 2)] = (sa1 & 0xFFFF0000u) | (sa0 >> 16);
            u32 sb0 = packsplit(r0.y * mv0);
            u32 sb1 = packsplit(r1.y * mv1);
            Oh[obase2 + (2 * ip + 1) * (L / 2)] = ((sb1 & 0xFFFFu) << 16) | (sb0 & 0xFFFFu);
            Ol[obase2 + (2 * ip + 1) * (L / 2)] = (sb1 & 0xFFFF0000u) | (sb0 >> 16);
        }
    }
}

// ---------------------------------------------------------------------------
// Kernel 2: fused attention (R13 structure) — epilogue writes hi/lo planes.
// ---------------------------------------------------------------------------
#define QP 48
#define KP 72
#define SM_QSH 0
#define SM_QSL 12288
#define SM_STG 24576
#define STG_BYTES 18432
#define PL_BYTES 4608
#define SM_MK  61440
#define SM_TOT 61952

__global__ __launch_bounds__(256, 2) void attn_kernel(const float* __restrict__ mask)
{
    extern __shared__ char smb[];
    unsigned short* Qsh = (unsigned short*)(smb + SM_QSH);
    unsigned short* Qsl = (unsigned short*)(smb + SM_QSL);

    const int bh = blockIdx.y;
    const int b = bh / H;
    const int row0 = blockIdx.x * 128;

    const u32* __restrict__ qb = g_qp + bh * DK * L;
    const unsigned short* __restrict__ khg = (const unsigned short*)g_kh + (size_t)bh * DK * L;
    const unsigned short* __restrict__ klg = (const unsigned short*)g_kl + (size_t)bh * DK * L;
    const unsigned short* __restrict__ vhg = (const unsigned short*)g_vh + (size_t)bh * DK * L;
    const unsigned short* __restrict__ vlg = (const unsigned short*)g_vl + (size_t)bh * DK * L;
    const float* __restrict__ mp = mask + b * L;

    const int t = threadIdx.x;
    const int lane = t & 31;
    const int warp = t >> 5;
    const int R0 = warp * 16;
    const int qid = lane & 3;

    const int fc = t >> 3;
    const int fch = t & 7;
    const size_t gofs = (size_t)fc * L + fch * 8;
    const u32 sofs = (u32)(fc * (KP * 2) + fch * 16);

    // ---- Q fill ----
    #pragma unroll
    for (int i = 0; i < 8; i++) {
        int idx = i * 256 + t;
        int m = idx >> 4, cp = idx & 15;
        u32 q0 = qb[(2 * cp + 0) * L + row0 + m];
        u32 q1 = qb[(2 * cp + 1) * L + row0 + m];
        *(u32*)&Qsh[m * QP + 2 * cp] = ((q1 & 0xFFFFu) << 16) | (q0 & 0xFFFFu);
        *(u32*)&Qsl[m * QP + 2 * cp] = (q1 & 0xFFFF0000u) | (q0 >> 16);
    }

    // ---- issue tile 0 loads ----
    {
        u32 sb0 = smaddr(smb + SM_STG) + sofs;
        cpa16(sb0,                 khg + gofs);
        cpa16(sb0 + PL_BYTES,      klg + gofs);
        cpa16(sb0 + 2 * PL_BYTES,  vhg + gofs);
        cpa16(sb0 + 3 * PL_BYTES,  vlg + gofs);
        if (t < 16) cpa16(smaddr(smb + SM_MK) + t * 16, mp + t * 4);
    }
    asm volatile("cp.async.commit_group;");

    __syncthreads();

    // ---- Q fragments (persistent) ----
    u32 qah[2][4], qal[2][4];
    #pragma unroll
    for (int kt = 0; kt < 2; kt++) {
        int arow = R0 + (lane & 15);
        int acol = kt * 16 + (lane >> 4) * 8;
        ldsm4(qah[kt][0], qah[kt][1], qah[kt][2], qah[kt][3], smaddr(&Qsh[arow * QP + acol]));
        ldsm4(qal[kt][0], qal[kt][1], qal[kt][2], qal[kt][3], smaddr(&Qsl[arow * QP + acol]));
    }

    float oa[4][4];
    #pragma unroll
    for (int i = 0; i < 4; i++)
        #pragma unroll
        for (int j = 0; j < 4; j++) oa[i][j] = 0.f;
    float ps0 = 0.f, ps1 = 0.f;

    const int NTILES = L / 64;
    for (int it = 0; it < NTILES; it++) {
        const int cur = it & 1;

        if (it + 1 < NTILES) {
            int col0n = (it + 1) * 64;
            u32 sbn = smaddr(smb + SM_STG + (cur ^ 1) * STG_BYTES) + sofs;
            cpa16(sbn,                khg + gofs + col0n);
            cpa16(sbn + PL_BYTES,     klg + gofs + col0n);
            cpa16(sbn + 2 * PL_BYTES, vhg + gofs + col0n);
            cpa16(sbn + 3 * PL_BYTES, vlg + gofs + col0n);
            if (t < 16) cpa16(smaddr(smb + SM_MK + (cur ^ 1) * 256) + t * 16, mp + col0n + t * 4);
        }
        asm volatile("cp.async.commit_group;");
        asm volatile("cp.async.wait_group 1;");
        __syncthreads();

        unsigned short* Ksh = (unsigned short*)(smb + SM_STG + cur * STG_BYTES);
        unsigned short* Ksl = (unsigned short*)(smb + SM_STG + cur * STG_BYTES + PL_BYTES);
        unsigned short* Vsh = (unsigned short*)(smb + SM_STG + cur * STG_BYTES + 2 * PL_BYTES);
        unsigned short* Vsl = (unsigned short*)(smb + SM_STG + cur * STG_BYTES + 3 * PL_BYTES);
        const float* mk = (const float*)(smb + SM_MK + cur * 256);

        #pragma unroll
        for (int ktp = 0; ktp < 4; ktp++) {
            float sa[2][4];
            #pragma unroll
            for (int i = 0; i < 2; i++)
                #pragma unroll
                for (int j = 0; j < 4; j++) sa[i][j] = 0.f;

            #pragma unroll
            for (int kt = 0; kt < 2; kt++) {
                u32 addr_off = (u32)((kt * 16 + (lane & 15)) * KP + ktp * 16 + (lane >> 4) * 8);
                u32 bh0, bh1, bh2, bh3, bl0, bl1, bl2, bl3;
                ldsm4t(bh0, bh1, bh2, bh3, smaddr(&Ksh[addr_off]));
                ldsm4t(bl0, bl1, bl2, bl3, smaddr(&Ksl[addr_off]));
                mma16816(sa[0], qah[kt], bh0, bh1);
                mma16816(sa[0], qah[kt], bl0, bl1);
                mma16816(sa[0], qal[kt], bh0, bh1);
                mma16816(sa[1], qah[kt], bh2, bh3);
                mma16816(sa[1], qah[kt], bl2, bl3);
                mma16816(sa[1], qal[kt], bh2, bh3);
            }

            u32 pah[4], pal[4];
            #pragma unroll
            for (int od = 0; od < 2; od++) {
                int nj = 2 * ktp + od;
                float2 mm = *(const float2*)&mk[8 * nj + 2 * qid];
                float p0 = mm.x * __expf(sa[od][0]);
                float p1 = mm.y * __expf(sa[od][1]);
                float p2 = mm.x * __expf(sa[od][2]);
                float p3 = mm.y * __expf(sa[od][3]);
                ps0 += p0 + p1;
                ps1 += p2 + p3;
                u32 h01 = cvtbf2(p1, p0);
                u32 h23 = cvtbf2(p3, p2);
                float hf0 = __uint_as_float(h01 << 16);
                float hf1 = __uint_as_float(h01 & 0xFFFF0000u);
                float hf2 = __uint_as_float(h23 << 16);
                float hf3 = __uint_as_float(h23 & 0xFFFF0000u);
                pah[od * 2 + 0] = h01;
                pah[od * 2 + 1] = h23;
                pal[od * 2 + 0] = cvtbf2(p1 - hf1, p0 - hf0);
                pal[od * 2 + 1] = cvtbf2(p3 - hf3, p2 - hf2);
            }

            #pragma unroll
            for (int db = 0; db < 2; db++) {
                u32 addr_off = (u32)((db * 16 + (lane & 15)) * KP + ktp * 16 + (lane >> 4) * 8);
                u32 vh0, vh1, vh2, vh3, vl0, vl1, vl2, vl3;
                ldsm4(vh0, vh1, vh2, vh3, smaddr(&Vsh[addr_off]));
                ldsm4(vl0, vl1, vl2, vl3, smaddr(&Vsl[addr_off]));
                mma16816(oa[2 * db + 0], pah, vh0, vh2);
                mma16816(oa[2 * db + 0], pah, vl0, vl2);
                mma16816(oa[2 * db + 0], pal, vh0, vh2);
                mma16816(oa[2 * db + 1], pah, vh1, vh3);
                mma16816(oa[2 * db + 1], pah, vl1, vl3);
                mma16816(oa[2 * db + 1], pal, vh1, vh3);
            }
        }
        __syncthreads();
    }

    // ---- quad-reduce row sums ----
    ps0 += __shfl_xor_sync(0xFFFFFFFFu, ps0, 1);
    ps0 += __shfl_xor_sync(0xFFFFFFFFu, ps0, 2);
    ps1 += __shfl_xor_sync(0xFFFFFFFFu, ps1, 1);
    ps1 += __shfl_xor_sync(0xFFFFFFFFu, ps1, 2);
    const float inv0 = 1.0f / (ps0 + EPSV);
    const float inv1 = 1.0f / (ps1 + EPSV);

    // ---- store O as hi/lo planes (u32 pair stores) ----
    const int h = bh - b * H;
    const int r = row0 + R0 + (lane >> 2);
    const int cbase = h * DK + 2 * qid;
    #pragma unroll
    for (int dj = 0; dj < 4; dj++) {
        size_t e0 = ((size_t)(b * L + r) * D + cbase + 8 * dj) >> 1;
        size_t e1 = ((size_t)(b * L + r + 8) * D + cbase + 8 * dj) >> 1;
        u32 s0 = packsplit(oa[dj][0] * inv0);
        u32 s1 = packsplit(oa[dj][1] * inv0);
        u32 s2 = packsplit(oa[dj][2] * inv1);
        u32 s3 = packsplit(oa[dj][3] * inv1);
        ((u32*)g_oh)[e0] = ((s1 & 0xFFFFu) << 16) | (s0 & 0xFFFFu);
        ((u32*)g_ol)[e0] = (s1 & 0xFFFF0000u) | (s0 >> 16);
        ((u32*)g_oh)[e1] = ((s3 & 0xFFFFu) << 16) | (s2 & 0xFFFFu);
        ((u32*)g_ol)[e1] = (s3 & 0xFFFF0000u) | (s2 >> 16);
    }
}

// ---------------------------------------------------------------------------
// Kernel 3: out = mask * (Wp @ val + bp), bf16x3 tensor-core, cp.async fills.
// FIX vs R14: full fill coverage — 2 iterations x (row=idx>>3, chunk=idx&7)
// covers all 64 rows x 8 chunks per plane.
// ---------------------------------------------------------------------------
#define OP2 72                      // u16 pitch (144B rows)
#define OPL_BYTES 9216              // one 64-row plane
#define OSTG_BYTES 36864            // 4 planes (Ah, Al, Bh, Bl)
#define OSM_TOT 73728               // 2 stages

__global__ __launch_bounds__(256) void out_kernel(
    const float* __restrict__ bp, const float* __restrict__ mask,
    float* __restrict__ out)
{
    extern __shared__ char smb[];

    const int b = blockIdx.z;
    const int i0 = blockIdx.y * 64;
    const int l0 = blockIdx.x * 64;
    const int t = threadIdx.x;
    const int lane = t & 31;
    const int warp = t >> 5;
    const int R0 = (warp >> 1) * 16;
    const int C0 = (warp & 1) * 32;
    const int qid = lane & 3;

    const unsigned short* __restrict__ ah_g = g_oh + (size_t)b * L * D;
    const unsigned short* __restrict__ al_g = g_ol + (size_t)b * L * D;

    // fill coords (2 iterations): row = idx>>3 (0..63), chunk = idx&7 (0..7)
    int frow[2], fch[2];
    u32 sofs[2];
    size_t aofs[2], bofs[2];
    #pragma unroll
    for (int i = 0; i < 2; i++) {
        int idx = i * 256 + t;
        frow[i] = idx >> 3;
        fch[i] = idx & 7;
        sofs[i] = (u32)(frow[i] * (OP2 * 2) + fch[i] * 16);
        aofs[i] = (size_t)(l0 + frow[i]) * D + fch[i] * 8;   // + j0
        bofs[i] = (size_t)frow[i] * D + i0 + fch[i] * 8;     // + j0*D
    }

    // ---- issue chunk 0 ----
    #pragma unroll
    for (int i = 0; i < 2; i++) {
        u32 s0 = smaddr(smb) + sofs[i];
        cpa16(s0,                 ah_g + aofs[i]);
        cpa16(s0 + OPL_BYTES,     al_g + aofs[i]);
        cpa16(s0 + 2 * OPL_BYTES, g_wph + bofs[i]);
        cpa16(s0 + 3 * OPL_BYTES, g_wpl + bofs[i]);
    }
    asm volatile("cp.async.commit_group;");

    float oa[4][4];
    #pragma unroll
    for (int i = 0; i < 4; i++)
        #pragma unroll
        for (int j = 0; j < 4; j++) oa[i][j] = 0.f;

    const int NCH = D / 64;   // 4
    for (int ch = 0; ch < NCH; ch++) {
        const int cur = ch & 1;

        if (ch + 1 < NCH) {
            int jn = (ch + 1) * 64;
            #pragma unroll
            for (int i = 0; i < 2; i++) {
                u32 sn = smaddr(smb + (cur ^ 1) * OSTG_BYTES) + sofs[i];
                cpa16(sn,                 ah_g + aofs[i] + jn);
                cpa16(sn + OPL_BYTES,     al_g + aofs[i] + jn);
                cpa16(sn + 2 * OPL_BYTES, g_wph + bofs[i] + (size_t)jn * D);
                cpa16(sn + 3 * OPL_BYTES, g_wpl + bofs[i] + (size_t)jn * D);
            }
        }
        asm volatile("cp.async.commit_group;");
        asm volatile("cp.async.wait_group 1;");
        __syncthreads();

        unsigned short* Ash = (unsigned short*)(smb + cur * OSTG_BYTES);
        unsigned short* Asl = (unsigned short*)(smb + cur * OSTG_BYTES + OPL_BYTES);
        unsigned short* Bsh = (unsigned short*)(smb + cur * OSTG_BYTES + 2 * OPL_BYTES);
        unsigned short* Bsl = (unsigned short*)(smb + cur * OSTG_BYTES + 3 * OPL_BYTES);

        #pragma unroll
        for (int kt = 0; kt < 4; kt++) {
            int arow = R0 + (lane & 15);
            int acol = kt * 16 + (lane >> 4) * 8;
            u32 aah[4], aal[4];
            ldsm4(aah[0], aah[1], aah[2], aah[3], smaddr(&Ash[arow * OP2 + acol]));
            ldsm4(aal[0], aal[1], aal[2], aal[3], smaddr(&Asl[arow * OP2 + acol]));

            int brow = kt * 16 + (lane & 15);
            #pragma unroll
            for (int nbp = 0; nbp < 2; nbp++) {
                u32 addr_off = (u32)(brow * OP2 + C0 + nbp * 16 + (lane >> 4) * 8);
                u32 bh0, bh1, bh2, bh3, bl0, bl1, bl2, bl3;
                ldsm4t(bh0, bh1, bh2, bh3, smaddr(&Bsh[addr_off]));
                ldsm4t(bl0, bl1, bl2, bl3, smaddr(&Bsl[addr_off]));
                mma16816(oa[2 * nbp + 0], aah, bh0, bh1);
                mma16816(oa[2 * nbp + 0], aah, bl0, bl1);
                mma16816(oa[2 * nbp + 0], aal, bh0, bh1);
                mma16816(oa[2 * nbp + 1], aah, bh2, bh3);
                mma16816(oa[2 * nbp + 1], aah, bl2, bl3);
                mma16816(oa[2 * nbp + 1], aal, bh2, bh3);
            }
        }
        __syncthreads();
    }

    // ---- epilogue: bias + mask, fp32 stores ----
    const int r = R0 + (lane >> 2);
    const float m0 = mask[b * L + l0 + r];
    const float m1 = mask[b * L + l0 + r + 8];
    #pragma unroll
    for (int na = 0; na < 4; na++) {
        int col = i0 + C0 + na * 8 + 2 * qid;
        float2 bv = *(const float2*)&bp[col];
        *(float2*)&out[(size_t)(b * L + l0 + r) * D + col] =
            make_float2((oa[na][0] + bv.x) * m0, (oa[na][1] + bv.y) * m0);
        *(float2*)&out[(size_t)(b * L + l0 + r + 8) * D + col] =
            make_float2((oa[na][2] + bv.x) * m1, (oa[na][3] + bv.y) * m1);
    }
}

// ---------------------------------------------------------------------------
extern "C" void kernel_launch(void* const* d_in, const int* in_sizes, int n_in,
                              void* d_out, int out_size)
{
    const float* q    = (const float*)d_in[0];
    const float* k    = (const float*)d_in[1];
    const float* v    = (const float*)d_in[2];
    const float* mask = (const float*)d_in[3];
    const float* Wq   = (const float*)d_in[4];
    const float* Wk   = (const float*)d_in[5];
    const float* Wv   = (const float*)d_in[6];
    const float* Wp   = (const float*)d_in[7];
    const float* bp   = (const float*)d_in[8];
    float* out = (float*)d_out;

    cudaFuncSetAttribute(attn_kernel, cudaFuncAttributeMaxDynamicSharedMemorySize, SM_TOT);
    cudaFuncSetAttribute(out_kernel, cudaFuncAttributeMaxDynamicSharedMemorySize, OSM_TOT);

    wsplit_kernel<<<256, 256>>>(Wp);
    proj_kernel<<<dim3(L / 512, H, BS * 3), 256>>>(q, k, v, mask, Wq, Wk, Wv);
    attn_kernel<<<dim3(L / 128, BS * H), 256, SM_TOT>>>(mask);
    out_kernel<<<dim3(L / 64, D / 64, BS), 256, OSM_TOT>>>(bp, mask, out);
}